// round 8
// baseline (speedup 1.0000x reference)
#include <cuda_runtime.h>

// Problem constants (from reference)
#define KORD 8
#define NUMI 15
#define GBAS (NUMI + KORD)        // 23 basis functions
#define BB 1024
#define NN 34
#define HH 256
#define WW 256
#define NPTS (BB * NN)            // 34816 points
#define CH_STRIDE (HH * WW)       // 65536 floats between channels

// Scratch for the overlapped compute phase (device globals: allowed).
__device__ float g_p[NPTS];       // spline result (channel 0 value)
__device__ float g_pw[NPTS];      // raw power (channel 1 value)
__device__ int   g_off[NPTS];     // ch0 destination offset, or -1 if dead

// Order-8 B-spline KAN edge via local de Boor: only the K+1=9 basis functions
// covering x are nonzero. Uniform knots (h = 4/15) make every denominator in
// the triangular recurrence a compile-time constant -> pure FFMA, 9 registers.
// Out-of-range x: all indicators in the reference are zero, so the spline sum
// vanishes and only base*silu survives.
__device__ __forceinline__ float spline_apply_one(float x, int id,
                                                  const float* __restrict__ coef,
                                                  const float* __restrict__ base) {
    float res = base[id] * (x / (1.0f + expf(-x)));   // base * silu(x)

    const float invh = 15.0f / 4.0f;
    const float g0   = -2.0f - (float)KORD * (4.0f / 15.0f);  // grid[0]

    float u = (x - g0) * invh;                        // position in knot units
    float mf = floorf(u);
    int m = (int)mf;
    if (m < 0 || m > 30) return res;                  // outside knot range
    float t = u - mf;                                 // local coord in [0,1)

    // de Boor: N[r] = B_{m-8+r}(x) after the last iteration
    float N[KORD + 1];
    N[0] = 1.0f;
#pragma unroll
    for (int j = 1; j <= KORD; j++) {
        const float invj = 1.0f / (float)j;           // compile-time constant
        float saved = 0.0f;
#pragma unroll
        for (int r = 0; r < j; r++) {
            float temp = N[r] * invj;
            N[r] = saved + ((float)(r + 1) - t) * temp;
            saved = (t + (float)(j - 1 - r)) * temp;
        }
        N[j] = saved;
    }

    const float* crow = coef + id * GBAS;
#pragma unroll
    for (int r = 0; r <= KORD; r++) {
        int jdx = m - KORD + r;
        if (jdx >= 0 && jdx < GBAS)
            res += crow[jdx] * N[r];
    }
    return res;
}

// Compute phase: runs CONCURRENTLY with the memset (forked stream). One block
// per image, 64 threads; stages the image's xv row in smem, resolves
// last-write-wins collisions, evaluates the stacked splines, and writes
// (value, power, dest-offset) to scratch. Does NOT touch `out`.
__global__ void __launch_bounds__(64)
compute_kernel(const float* __restrict__ xv,
               const float* __restrict__ dcoef,
               const float* __restrict__ dbase,
               const float* __restrict__ ccoef,
               const float* __restrict__ cbase) {
    __shared__ float s_xv[NN * 5];
    __shared__ int   s_cx[NN];
    __shared__ int   s_cy[NN];

    const int b = blockIdx.x;
    const int tid = threadIdx.x;
    const float* vb = xv + (size_t)b * NN * 5;

#pragma unroll
    for (int i = tid; i < NN * 5; i += 64) s_xv[i] = vb[i];
    __syncthreads();

    const int n = tid;
    if (n >= NN) return;

    int cx = (int)rintf(s_xv[n * 5 + 1]);
    int cy = (int)rintf(s_xv[n * 5 + 2]);
    s_cx[n] = cx;
    s_cy[n] = cy;
    __syncthreads();

    float power = s_xv[n * 5 + 0];
    int dev = (int)s_xv[n * 5 + 3];
    int cat = (int)s_xv[n * 5 + 4];

    // Last-write-wins in index order: dead if any LATER point collides.
    bool dead = false;
#pragma unroll 4
    for (int m = n + 1; m < NN; m++)
        dead |= (s_cx[m] == cx) & (s_cy[m] == cy);

    const int idx = b * NN + n;
    if (dead) { g_off[idx] = -1; return; }

    float p = spline_apply_one(power, dev, dcoef, dbase);
    p       = spline_apply_one(p,     cat, ccoef, cbase);

    g_p[idx]   = p;
    g_pw[idx]  = power;
    g_off[idx] = b * (2 * CH_STRIDE) + cy * WW + cx;   // < 2^27, fits int
}

// Apply phase: after memset AND compute have both finished. One thread per
// point: one coalesced scratch read, two scattered stores. No compute.
__global__ void __launch_bounds__(256)
apply_kernel(float* __restrict__ out) {
    int idx = blockIdx.x * blockDim.x + threadIdx.x;
    if (idx >= NPTS) return;
    int off = g_off[idx];
    if (off < 0) return;
    out[off]             = g_p[idx];    // channel 0
    out[off + CH_STRIDE] = g_pw[idx];   // channel 1
}

extern "C" void kernel_launch(void* const* d_in, const int* in_sizes, int n_in,
                              void* d_out, int out_size) {
    const float* xv    = (const float*)d_in[0]; // (1024,34,5)
    const float* dcoef = (const float*)d_in[1]; // (34,23)
    const float* dbase = (const float*)d_in[2]; // (34,)
    const float* ccoef = (const float*)d_in[3]; // (5,23)
    const float* cbase = (const float*)d_in[4]; // (5,)
    float* out = (float*)d_out;                 // (1024,2,256,256)

    // Side stream + fork/join events. Created per call and deliberately not
    // destroyed: destroying a stream that is part of an active capture
    // invalidates the capture, and kernel_launch only runs O(1) times
    // (correctness + capture), so the leak is bounded and host-side.
    cudaStream_t s2;
    cudaStreamCreateWithFlags(&s2, cudaStreamNonBlocking);
    cudaEvent_t eFork, eJoin;
    cudaEventCreateWithFlags(&eFork, cudaEventDisableTiming);
    cudaEventCreateWithFlags(&eJoin, cudaEventDisableTiming);

    // Fork: bring s2 into the captured DAG.
    cudaEventRecord(eFork, 0);
    cudaStreamWaitEvent(s2, eFork, 0);

    // Overlapped: spline compute into scratch (s2) || bulk zero-fill (stream 0).
    compute_kernel<<<BB, 64, 0, s2>>>(xv, dcoef, dbase, ccoef, cbase);
    cudaMemsetAsync(out, 0, (size_t)out_size * sizeof(float), 0);

    // Join: apply after both the memset (stream order) and compute (event).
    cudaEventRecord(eJoin, s2);
    cudaStreamWaitEvent(0, eJoin, 0);

    apply_kernel<<<(NPTS + 255) / 256, 256>>>(out);
}

// round 9
// speedup vs baseline: 1.0156x; 1.0156x over previous
#include <cuda_runtime.h>

// Problem constants (from reference)
#define KORD 8
#define NUMI 15
#define GBAS (NUMI + KORD)        // 23 basis functions
#define BB 1024
#define NN 34
#define HH 256
#define WW 256
#define IMG_FLOATS (2 * HH * WW)  // 131072 floats per image
#define CH_STRIDE (HH * WW)

// Image-range split: memsetA covers [0,SPLIT), memsetB covers [SPLIT,BB).
// scatterA overlaps memsetB; scatterB (small) is the only serial tail.
#define SPLIT 768

// Order-8 B-spline KAN edge via local de Boor: only the K+1=9 basis functions
// covering x are nonzero. Uniform knots (h = 4/15) make every denominator in
// the triangular recurrence a compile-time constant -> pure FFMA, 9 registers.
// Out-of-range x: all reference indicators are zero -> only base*silu survives.
// `coef`/`base` may point to global or shared memory (generic loads).
__device__ __forceinline__ float spline_apply_one(float x, int id,
                                                  const float* coef,
                                                  const float* base) {
    float res = base[id] * (x / (1.0f + expf(-x)));   // base * silu(x)

    const float invh = 15.0f / 4.0f;
    const float g0   = -2.0f - (float)KORD * (4.0f / 15.0f);  // grid[0]

    float u = (x - g0) * invh;                        // position in knot units
    float mf = floorf(u);
    int m = (int)mf;
    if (m < 0 || m > 30) return res;                  // outside knot range
    float t = u - mf;                                 // local coord in [0,1)

    // de Boor: N[r] = B_{m-8+r}(x) after the last iteration
    float N[KORD + 1];
    N[0] = 1.0f;
#pragma unroll
    for (int j = 1; j <= KORD; j++) {
        const float invj = 1.0f / (float)j;           // compile-time constant
        float saved = 0.0f;
#pragma unroll
        for (int r = 0; r < j; r++) {
            float temp = N[r] * invj;
            N[r] = saved + ((float)(r + 1) - t) * temp;
            saved = (t + (float)(j - 1 - r)) * temp;
        }
        N[j] = saved;
    }

    const float* crow = coef + id * GBAS;
#pragma unroll
    for (int r = 0; r <= KORD; r++) {
        int jdx = m - KORD + r;
        if (jdx >= 0 && jdx < GBAS)
            res += crow[jdx] * N[r];
    }
    return res;
}

// One block per image (image index = img_base + blockIdx.x), 64 threads.
// Stages the image's xv row AND the stage-2 tables (ccoef/cbase, 120 floats)
// in smem, resolves last-write-wins collisions, evaluates the stacked
// splines, scatters two stores into the (already-zeroed) image.
__global__ void __launch_bounds__(64)
scatter_kernel(const float* __restrict__ xv,
               const float* __restrict__ dcoef,
               const float* __restrict__ dbase,
               const float* __restrict__ ccoef,
               const float* __restrict__ cbase,
               float* __restrict__ out,
               int img_base) {
    __shared__ float s_xv[NN * 5];     // 680 B
    __shared__ float s_cc[5 * GBAS + 5]; // ccoef (115) + cbase (5)
    __shared__ int   s_cx[NN];
    __shared__ int   s_cy[NN];

    const int b = img_base + blockIdx.x;
    const int tid = threadIdx.x;
    const float* vb = xv + (size_t)b * NN * 5;

    // Coalesced stage of the image row and the stage-2 spline tables.
#pragma unroll
    for (int i = tid; i < NN * 5; i += 64) s_xv[i] = vb[i];
#pragma unroll
    for (int i = tid; i < 5 * GBAS + 5; i += 64)
        s_cc[i] = (i < 5 * GBAS) ? ccoef[i] : cbase[i - 5 * GBAS];
    __syncthreads();

    const int n = tid;
    if (n >= NN) return;

    int cx = (int)rintf(s_xv[n * 5 + 1]);
    int cy = (int)rintf(s_xv[n * 5 + 2]);
    s_cx[n] = cx;
    s_cy[n] = cy;
    __syncthreads();

    float power = s_xv[n * 5 + 0];
    int dev = (int)s_xv[n * 5 + 3];
    int cat = (int)s_xv[n * 5 + 4];

    // Last-write-wins in index order: dead if any LATER point collides.
    bool dead = false;
#pragma unroll 4
    for (int m = n + 1; m < NN; m++)
        dead |= (s_cx[m] == cx) & (s_cy[m] == cy);
    if (dead) return;

    float p = spline_apply_one(power, dev, dcoef, dbase);
    p       = spline_apply_one(p,     cat, s_cc, s_cc + 5 * GBAS);

    size_t base_off = (size_t)b * IMG_FLOATS;
    size_t pix = (size_t)cy * WW + cx;
    out[base_off + pix] = p;                 // channel 0
    out[base_off + CH_STRIDE + pix] = power; // channel 1
}

extern "C" void kernel_launch(void* const* d_in, const int* in_sizes, int n_in,
                              void* d_out, int out_size) {
    const float* xv    = (const float*)d_in[0]; // (1024,34,5)
    const float* dcoef = (const float*)d_in[1]; // (34,23)
    const float* dbase = (const float*)d_in[2]; // (34,)
    const float* ccoef = (const float*)d_in[3]; // (5,23)
    const float* cbase = (const float*)d_in[4]; // (5,)
    float* out = (float*)d_out;                 // (1024,2,256,256)

    // Side stream + events for the fork/join. Created per call and not
    // destroyed (destroying a stream inside an active capture invalidates
    // it; kernel_launch runs O(1) times, so the host-side leak is bounded).
    cudaStream_t s2;
    cudaStreamCreateWithFlags(&s2, cudaStreamNonBlocking);
    cudaEvent_t eA, eS;
    cudaEventCreateWithFlags(&eA, cudaEventDisableTiming);
    cudaEventCreateWithFlags(&eS, cudaEventDisableTiming);

    const size_t imgBytes = (size_t)IMG_FLOATS * sizeof(float);

    // memsetA: images [0, SPLIT)  (stream 0)
    cudaMemsetAsync(out, 0, (size_t)SPLIT * imgBytes, 0);
    cudaEventRecord(eA, 0);

    // scatterA on side stream — overlaps memsetB below.
    cudaStreamWaitEvent(s2, eA, 0);
    scatter_kernel<<<SPLIT, 64, 0, s2>>>(xv, dcoef, dbase, ccoef, cbase, out, 0);
    cudaEventRecord(eS, s2);

    // memsetB: images [SPLIT, BB)  (stream 0, concurrent with scatterA)
    cudaMemsetAsync(out + (size_t)SPLIT * IMG_FLOATS, 0,
                    (size_t)(BB - SPLIT) * imgBytes, 0);

    // scatterB: small serial tail on stream 0, joined with scatterA.
    cudaStreamWaitEvent(0, eS, 0);
    scatter_kernel<<<BB - SPLIT, 64, 0, 0>>>(xv, dcoef, dbase, ccoef, cbase,
                                             out, SPLIT);
}

// round 10
// speedup vs baseline: 1.0439x; 1.0279x over previous
#include <cuda_runtime.h>

// Problem constants (from reference)
#define KORD 8
#define NUMI 15
#define GBAS (NUMI + KORD)        // 23 basis functions
#define BB 1024
#define NN 34
#define HH 256
#define WW 256
#define IMG_FLOATS (2 * HH * WW)  // 131072 floats per image
#define CH_STRIDE (HH * WW)
#define IMG_PER_BLK 4
#define NBLK (BB / IMG_PER_BLK)   // 256 blocks

// Order-8 B-spline KAN edge via local de Boor: only the K+1=9 basis functions
// covering x are nonzero. Uniform knots (h = 4/15) make every denominator in
// the triangular recurrence a compile-time constant -> pure FFMA, 9 registers.
// Out-of-range x: all reference indicators are zero -> only base*silu survives.
// coef/base point to SHARED memory (staged tables) — chain is regs + LDS only.
__device__ __forceinline__ float spline_apply_one(float x, int id,
                                                  const float* coef,
                                                  const float* base) {
    // base * silu(x); fast intrinsics (tolerance 1e-3, current err ~7e-8)
    float res = base[id] * __fdividef(x, 1.0f + __expf(-x));

    const float invh = 15.0f / 4.0f;
    const float g0   = -2.0f - (float)KORD * (4.0f / 15.0f);  // grid[0]

    float u = (x - g0) * invh;                        // position in knot units
    float mf = floorf(u);
    int m = (int)mf;
    if (m < 0 || m > 30) return res;                  // outside knot range
    float t = u - mf;                                 // local coord in [0,1)

    // de Boor: N[r] = B_{m-8+r}(x) after the last iteration
    float N[KORD + 1];
    N[0] = 1.0f;
#pragma unroll
    for (int j = 1; j <= KORD; j++) {
        const float invj = 1.0f / (float)j;           // compile-time constant
        float saved = 0.0f;
#pragma unroll
        for (int r = 0; r < j; r++) {
            float temp = N[r] * invj;
            N[r] = saved + ((float)(r + 1) - t) * temp;
            saved = (t + (float)(j - 1 - r)) * temp;
        }
        N[j] = saved;
    }

    const float* crow = coef + id * GBAS;
    float s = res;
#pragma unroll
    for (int r = 0; r <= KORD; r++) {
        int jdx = m - KORD + r;
        if (jdx >= 0 && jdx < GBAS)
            s += crow[jdx] * N[r];
    }
    return s;
}

// 4 images per 256-thread block (256 blocks). Stage: the 4 contiguous xv rows
// (2720 B, one coalesced burst) AND the full spline tables (dcoef/dbase +
// ccoef/cbase, ~3.8 KB) — table loads are independent of xv, full MLP. Each
// 64-thread sub-group owns one image: smem collision scan (last-write-wins),
// two stacked spline evals entirely from regs+LDS, two scattered stores.
__global__ void __launch_bounds__(256)
scatter_kernel(const float* __restrict__ xv,
               const float* __restrict__ dcoef,
               const float* __restrict__ dbase,
               const float* __restrict__ ccoef,
               const float* __restrict__ cbase,
               float* __restrict__ out) {
    __shared__ float s_xv[IMG_PER_BLK * NN * 5];   // 680 floats
    __shared__ float s_dc[34 * GBAS];              // 782 floats
    __shared__ float s_db[34];
    __shared__ float s_cc[5 * GBAS];               // 115 floats
    __shared__ float s_cb[5];
    __shared__ int   s_cx[IMG_PER_BLK][NN];
    __shared__ int   s_cy[IMG_PER_BLK][NN];

    const int tid = threadIdx.x;
    const int b0 = blockIdx.x * IMG_PER_BLK;
    const float* vb = xv + (size_t)b0 * NN * 5;

    // All staging loads issued together (independent -> overlapping latency)
#pragma unroll
    for (int i = tid; i < IMG_PER_BLK * NN * 5; i += 256) s_xv[i] = vb[i];
#pragma unroll
    for (int i = tid; i < 34 * GBAS; i += 256) s_dc[i] = dcoef[i];
    if (tid < 34) s_db[tid] = dbase[tid];
    else if (tid >= 64 && tid < 64 + 5 * GBAS) s_cc[tid - 64] = ccoef[tid - 64];
    else if (tid >= 192 && tid < 197) s_cb[tid - 192] = cbase[tid - 192];
    __syncthreads();

    const int sub = tid >> 6;          // image within block (0..3)
    const int n = tid & 63;            // point within image
    const float* sv = s_xv + sub * NN * 5;

    int cx = 0, cy = 0;
    if (n < NN) {
        cx = (int)rintf(sv[n * 5 + 1]);
        cy = (int)rintf(sv[n * 5 + 2]);
        s_cx[sub][n] = cx;
        s_cy[sub][n] = cy;
    }
    __syncthreads();

    if (n >= NN) return;

    float power = sv[n * 5 + 0];
    int dev = (int)sv[n * 5 + 3];
    int cat = (int)sv[n * 5 + 4];

    // Last-write-wins in index order: dead if any LATER point collides.
    bool dead = false;
#pragma unroll 4
    for (int m = n + 1; m < NN; m++)
        dead |= (s_cx[sub][m] == cx) & (s_cy[sub][m] == cy);
    if (dead) return;

    float p = spline_apply_one(power, dev, s_dc, s_db);
    p       = spline_apply_one(p,     cat, s_cc, s_cb);

    size_t base_off = (size_t)(b0 + sub) * IMG_FLOATS;
    size_t pix = (size_t)cy * WW + cx;
    out[base_off + pix] = p;                  // channel 0
    out[base_off + CH_STRIDE + pix] = power;  // channel 1
}

extern "C" void kernel_launch(void* const* d_in, const int* in_sizes, int n_in,
                              void* d_out, int out_size) {
    const float* xv    = (const float*)d_in[0]; // (1024,34,5)
    const float* dcoef = (const float*)d_in[1]; // (34,23)
    const float* dbase = (const float*)d_in[2]; // (34,)
    const float* ccoef = (const float*)d_in[3]; // (5,23)
    const float* cbase = (const float*)d_in[4]; // (5,)
    float* out = (float*)d_out;                 // (1024,2,256,256)

    // Phase 1: single driver bulk zero-fill (~7.2 TB/s, at the write roofline).
    cudaMemsetAsync(out, 0, (size_t)out_size * sizeof(float), 0);

    // Phase 2: sparse scatter, 4 images per block.
    scatter_kernel<<<NBLK, 256>>>(xv, dcoef, dbase, ccoef, cbase, out);
}